// round 1
// baseline (speedup 1.0000x reference)
#include <cuda_runtime.h>

// Problem constants (fixed by the dataset): B=16, S=2048, D=128, fp32.
#define BATCH 16
#define SEQ   2048
#define DIM   128
#define ROWS  16      // K-rows (weight rows) per block
#define JT    128     // j-tile width
#define NTHREADS 256
#define SPAD  129     // padded row stride for staging tile (conflict-free: 129 % 32 == 1)

// SMEM layout (floats):
//   sA : ROWS*DIM           = 2048    (scaled K rows)
//   sS : ROWS*SEQ           = 32768   (score / weight row buffer)
//   sT : JT*SPAD            = 16512   (staging: Q tile, then V tile)
// total = 51328 floats = 205312 bytes

__global__ void __launch_bounds__(NTHREADS, 1)
attn_rows_kernel(const float* __restrict__ Q, const float* __restrict__ K,
                 const float* __restrict__ V, float* __restrict__ outO,
                 float* __restrict__ outW)
{
    extern __shared__ float sm[];
    float* sA = sm;                    // [ROWS][DIM]
    float* sS = sm + ROWS * DIM;       // [ROWS][SEQ]
    float* sT = sS + ROWS * SEQ;       // [JT][SPAD]

    const int b   = blockIdx.y;
    const int i0  = blockIdx.x * ROWS;          // first weight-row of this block
    const int tid = threadIdx.x;

    const float scale = 0.08838834764831845f;   // 1/sqrt(128)

    // ---- Load K rows i0..i0+15, pre-scaled by 1/sqrt(d) ----
    {
        const float4* Kp = (const float4*)(K + ((size_t)b * SEQ + i0) * DIM);
        #pragma unroll
        for (int idx = tid; idx < ROWS * DIM / 4; idx += NTHREADS) {
            float4 v = Kp[idx];
            v.x *= scale; v.y *= scale; v.z *= scale; v.w *= scale;
            ((float4*)sA)[idx] = v;
        }
    }
    __syncthreads();

    const int jt0 = i0 / JT;        // first j-tile with any unmasked entry
    const int jlo = jt0 * JT;

    const int rg = tid >> 6;        // row group 0..3  (rows 4*rg .. 4*rg+3)
    const int cg = tid & 63;        // col group 0..63 (cols cg, cg+64)

    // =======================  Phase A: scores  =======================
    for (int jt = jt0; jt < SEQ / JT; ++jt) {
        const int j0 = jt * JT;
        // Load Q tile [j0 .. j0+127][0..127] into sT[j][k] (padded rows)
        {
            const float* Qp = Q + ((size_t)b * SEQ + j0) * DIM;
            #pragma unroll
            for (int idx = tid; idx < JT * DIM / 4; idx += NTHREADS) {
                int j  = idx >> 5;      // DIM/4 = 32 float4 per row
                int k4 = idx & 31;
                float4 v = ((const float4*)(Qp + j * DIM))[k4];
                float* dst = sT + j * SPAD + k4 * 4;
                dst[0] = v.x; dst[1] = v.y; dst[2] = v.z; dst[3] = v.w;
            }
        }
        __syncthreads();

        // 4x2 microtile: rows 4*rg..+3, cols cg and cg+64
        float acc00 = 0.f, acc01 = 0.f, acc10 = 0.f, acc11 = 0.f;
        float acc20 = 0.f, acc21 = 0.f, acc30 = 0.f, acc31 = 0.f;
        const float* a0 = sA + (4 * rg + 0) * DIM;
        const float* a1 = sA + (4 * rg + 1) * DIM;
        const float* a2 = sA + (4 * rg + 2) * DIM;
        const float* a3 = sA + (4 * rg + 3) * DIM;
        const float* q0 = sT + cg * SPAD;
        const float* q1 = sT + (cg + 64) * SPAD;
        #pragma unroll 8
        for (int k = 0; k < DIM; ++k) {
            float qa = q0[k];
            float qb = q1[k];
            float x0 = a0[k], x1 = a1[k], x2 = a2[k], x3 = a3[k];
            acc00 = fmaf(x0, qa, acc00); acc01 = fmaf(x0, qb, acc01);
            acc10 = fmaf(x1, qa, acc10); acc11 = fmaf(x1, qb, acc11);
            acc20 = fmaf(x2, qa, acc20); acc21 = fmaf(x2, qb, acc21);
            acc30 = fmaf(x3, qa, acc30); acc31 = fmaf(x3, qb, acc31);
        }

        // Write scores to sS with mask (j < i -> -1e7, matching reference)
        {
            float accA[4] = {acc00, acc10, acc20, acc30};
            float accB[4] = {acc01, acc11, acc21, acc31};
            const int jA = j0 + cg;
            const int jB = j0 + cg + 64;
            #pragma unroll
            for (int r4 = 0; r4 < 4; ++r4) {
                int r = 4 * rg + r4;
                int i = i0 + r;
                sS[r * SEQ + jA] = (jA < i) ? -1.0e7f : accA[r4];
                sS[r * SEQ + jB] = (jB < i) ? -1.0e7f : accB[r4];
            }
        }
        __syncthreads();   // protect sT before next tile load
    }

    // =======================  Softmax + weights writeback  =======================
    {
        const int wid  = tid >> 5;
        const int lane = tid & 31;
        for (int r = wid; r < ROWS; r += NTHREADS / 32) {
            float* row = sS + r * SEQ;
            float mx = -3.0e38f;
            for (int j = jlo + lane; j < SEQ; j += 32) mx = fmaxf(mx, row[j]);
            #pragma unroll
            for (int o = 16; o; o >>= 1) mx = fmaxf(mx, __shfl_xor_sync(0xffffffffu, mx, o));

            float sum = 0.f;
            for (int j = jlo + lane; j < SEQ; j += 32) {
                float e = __expf(row[j] - mx);   // masked entries underflow to exact 0
                row[j] = e;
                sum += e;
            }
            #pragma unroll
            for (int o = 16; o; o >>= 1) sum += __shfl_xor_sync(0xffffffffu, sum, o);
            float inv = 1.0f / sum;

            float* wrow = outW + ((size_t)b * SEQ + (i0 + r)) * SEQ;
            for (int j = lane; j < jlo; j += 32) wrow[j] = 0.0f;     // fully-masked prefix
            for (int j = jlo + lane; j < SEQ; j += 32) {
                float w = row[j] * inv;
                row[j] = w;
                wrow[j] = w;
            }
        }
    }
    __syncthreads();

    // =======================  Phase B: outputs = weights @ V  =======================
    float o00 = 0.f, o01 = 0.f, o10 = 0.f, o11 = 0.f;
    float o20 = 0.f, o21 = 0.f, o30 = 0.f, o31 = 0.f;
    for (int jt = jt0; jt < SEQ / JT; ++jt) {
        const int j0 = jt * JT;
        // Load V tile into sT[j][d] (padded rows)
        {
            const float* Vp = V + ((size_t)b * SEQ + j0) * DIM;
            #pragma unroll
            for (int idx = tid; idx < JT * DIM / 4; idx += NTHREADS) {
                int j  = idx >> 5;
                int k4 = idx & 31;
                float4 v = ((const float4*)(Vp + j * DIM))[k4];
                float* dst = sT + j * SPAD + k4 * 4;
                dst[0] = v.x; dst[1] = v.y; dst[2] = v.z; dst[3] = v.w;
            }
        }
        __syncthreads();

        const float* w0 = sS + (4 * rg + 0) * SEQ + j0;
        const float* w1 = sS + (4 * rg + 1) * SEQ + j0;
        const float* w2 = sS + (4 * rg + 2) * SEQ + j0;
        const float* w3 = sS + (4 * rg + 3) * SEQ + j0;
        #pragma unroll 8
        for (int j = 0; j < JT; ++j) {
            float va = sT[j * SPAD + cg];
            float vb = sT[j * SPAD + cg + 64];
            float x0 = w0[j], x1 = w1[j], x2 = w2[j], x3 = w3[j];
            o00 = fmaf(x0, va, o00); o01 = fmaf(x0, vb, o01);
            o10 = fmaf(x1, va, o10); o11 = fmaf(x1, vb, o11);
            o20 = fmaf(x2, va, o20); o21 = fmaf(x2, vb, o21);
            o30 = fmaf(x3, va, o30); o31 = fmaf(x3, vb, o31);
        }
        __syncthreads();
    }

    // Write outputs
    {
        float oa[4] = {o00, o10, o20, o30};
        float ob[4] = {o01, o11, o21, o31};
        #pragma unroll
        for (int r4 = 0; r4 < 4; ++r4) {
            int r = 4 * rg + r4;
            float* orow = outO + ((size_t)b * SEQ + (i0 + r)) * DIM;
            orow[cg]      = oa[r4];
            orow[cg + 64] = ob[r4];
        }
    }
}

extern "C" void kernel_launch(void* const* d_in, const int* in_sizes, int n_in,
                              void* d_out, int out_size)
{
    const float* Q = (const float*)d_in[0];
    const float* K = (const float*)d_in[1];
    const float* V = (const float*)d_in[2];
    float* out  = (float*)d_out;
    float* outO = out;                                        // (B,S,D)
    float* outW = out + (size_t)BATCH * SEQ * DIM;            // (B,S,S)

    const size_t smem_bytes =
        (size_t)(ROWS * DIM + ROWS * SEQ + JT * SPAD) * sizeof(float);  // 205312

    cudaFuncSetAttribute(attn_rows_kernel,
                         cudaFuncAttributeMaxDynamicSharedMemorySize,
                         (int)smem_bytes);

    dim3 grid(SEQ / ROWS, BATCH);
    attn_rows_kernel<<<grid, NTHREADS, smem_bytes>>>(Q, K, V, outO, outW);
}